// round 4
// baseline (speedup 1.0000x reference)
#include <cuda_runtime.h>

#define Bn 4
#define Cn 64
#define Hn 180
#define Wn 320
#define HW (Hn*Wn)            // 57600
#define CHW (Cn*HW)           // 3686400
#define BCHW (Bn*CHW)         // 14745600
#define BH (Bn*Hn)            // 720
#define WW (Wn*Wn)            // 102400
#define EPSV 1e-6f

typedef unsigned long long u64;

// ---- packed f32x2 helpers (sm_103a FFMA2 path, PTX-only) ----
__device__ __forceinline__ u64 pack2(float lo, float hi) {
    u64 r; asm("mov.b64 %0,{%1,%2};" : "=l"(r) : "f"(lo), "f"(hi)); return r;
}
__device__ __forceinline__ void ffma2(u64& d, u64 a, u64 b) {
    asm("fma.rn.f32x2 %0,%1,%2,%3;" : "=l"(d) : "l"(a), "l"(b), "l"(d));
}
__device__ __forceinline__ float2 unpack2(u64 v) {
    float2 r; asm("mov.b64 {%0,%1},%2;" : "=f"(r.x), "=f"(r.y) : "l"(v)); return r;
}

// ---- scratch (allocation-free: static device globals) ----
__device__ float g_Ql[BCHW];
__device__ float g_Qr[BCHW];
__device__ float g_Vl[BCHW];
__device__ float g_Vr[BCHW];
__device__ float g_attn [BH*WW];   // [bh, w, v]
__device__ float g_attnT[BH*WW];   // [bh, v, w]

// ============================================================
// K1: per-pixel LayerNorm + Q/V 1x1-conv projections (FFMA2).
// ============================================================
__global__ __launch_bounds__(256,2) void k_proj(
    const float* __restrict__ x,
    const float* __restrict__ lnw, const float* __restrict__ lnb,
    const float* __restrict__ wq,  const float* __restrict__ bq,
    const float* __restrict__ wv,  const float* __restrict__ bv,
    int side)
{
    extern __shared__ float sm[];
    float* s_x  = sm;                 // 64*256
    float* s_wq = s_x + Cn*256;       // 4096
    float* s_wv = s_wq + Cn*Cn;       // 4096
    float* s_bq = s_wv + Cn*Cn;       // 64
    float* s_rs = s_bq + Cn;          // 64
    float* s_bv = s_rs + Cn;          // 64

    float* Qo = side ? g_Qr : g_Ql;
    float* Vo = side ? g_Vr : g_Vl;

    const int t    = threadIdx.x;
    const int pix0 = blockIdx.x * 256;
    const int b    = pix0 / HW;
    const int hw0  = pix0 - b*HW;
    const int base = b*CHW + hw0;

    for (int i = t; i < Cn*Cn; i += 256) {
        s_wq[i] = wq[i] * lnw[i & (Cn-1)];
        s_wv[i] = wv[i];
    }
    if (t < Cn) {
        float bb = bq[t], rs = 0.f;
        #pragma unroll
        for (int ci = 0; ci < Cn; ci++) {
            bb += wq[t*Cn+ci]*lnb[ci];
            rs += wv[t*Cn+ci];
        }
        s_bq[t] = bb; s_rs[t] = rs; s_bv[t] = bv[t];
    }
    #pragma unroll 8
    for (int c = 0; c < Cn; c++)
        s_x[c*256 + t] = x[base + c*HW + t];
    __syncthreads();

    float sum = 0.f, ss = 0.f;
    #pragma unroll
    for (int c = 0; c < Cn; c++) {
        float v = s_x[c*256 + t];
        sum += v; ss += v*v;
    }
    const float mu  = sum * (1.f/Cn);
    const float ve  = ss * (1.f/Cn) - mu*mu + EPSV;
    const float rsq = rsqrtf(ve);
    const float sd  = ve * rsq;               // sqrt(var+eps)

    // packed normalized activations
    u64 xnp[Cn/2];
    #pragma unroll
    for (int k = 0; k < Cn/2; k++)
        xnp[k] = pack2((s_x[(2*k)*256 + t]-mu)*rsq, (s_x[(2*k+1)*256 + t]-mu)*rsq);

    for (int co = 0; co < Cn; co++) {
        const ulonglong2* wq2 = reinterpret_cast<const ulonglong2*>(s_wq + co*Cn);
        const ulonglong2* wv2 = reinterpret_cast<const ulonglong2*>(s_wv + co*Cn);
        u64 aqA = 0, aqB = 0, avA = 0, avB = 0;   // 4 independent chains
        #pragma unroll
        for (int k = 0; k < Cn/4; k++) {
            ulonglong2 a = wq2[k], v2 = wv2[k];
            ffma2(aqA, a.x,  xnp[2*k]);
            ffma2(aqB, a.y,  xnp[2*k+1]);
            ffma2(avA, v2.x, xnp[2*k]);
            ffma2(avB, v2.y, xnp[2*k+1]);
        }
        float2 q1 = unpack2(aqA), q2 = unpack2(aqB);
        float2 v1 = unpack2(avA), v2u = unpack2(avB);
        float aq = (q1.x+q1.y) + (q2.x+q2.y);
        float av = (v1.x+v1.y) + (v2u.x+v2u.y);
        Qo[base + co*HW + t] = aq + s_bq[co];
        Vo[base + co*HW + t] = sd*av + mu*s_rs[co] + s_bv[co];
    }
}

// ============================================================
// K2: attn[bh,w,v] = scale * sum_c Ql[.,w]*Qr[.,v]  (FFMA2,
// w-pairs packed). Also writes transposed copy.
// ============================================================
__global__ __launch_bounds__(256) void k_attn()
{
    __shared__ float s_a[Cn*64];
    __shared__ float s_b[Cn*64];
    const int t  = threadIdx.x;
    const int w0 = blockIdx.x*64, v0 = blockIdx.y*64;
    const int bh = blockIdx.z;
    const int b  = bh / Hn, h = bh - b*Hn;
    const int qbase = b*CHW + h*Wn;

    for (int i = t; i < Cn*64; i += 256) {
        int c = i >> 6, j = i & 63;
        s_a[i] = g_Ql[qbase + c*HW + w0 + j];
        s_b[i] = g_Qr[qbase + c*HW + v0 + j];
    }
    __syncthreads();

    const int tx = t & 15, ty = t >> 4;
    u64 acc01[4] = {}, acc23[4] = {};   // w-pairs (w0w1),(w2w3) x 4 v
    #pragma unroll 4
    for (int c = 0; c < Cn; c++) {
        ulonglong2 au = *reinterpret_cast<const ulonglong2*>(&s_a[c*64 + tx*4]);
        float4 b4 = *reinterpret_cast<const float4*>(&s_b[c*64 + ty*4]);
        u64 bs0 = pack2(b4.x,b4.x), bs1 = pack2(b4.y,b4.y);
        u64 bs2 = pack2(b4.z,b4.z), bs3 = pack2(b4.w,b4.w);
        ffma2(acc01[0], au.x, bs0); ffma2(acc23[0], au.y, bs0);
        ffma2(acc01[1], au.x, bs1); ffma2(acc23[1], au.y, bs1);
        ffma2(acc01[2], au.x, bs2); ffma2(acc23[2], au.y, bs2);
        ffma2(acc01[3], au.x, bs3); ffma2(acc23[3], au.y, bs3);
    }
    float acc[4][4];
    #pragma unroll
    for (int iv = 0; iv < 4; iv++) {
        float2 lo = unpack2(acc01[iv]), hi = unpack2(acc23[iv]);
        acc[0][iv] = lo.x; acc[1][iv] = lo.y; acc[2][iv] = hi.x; acc[3][iv] = hi.y;
    }
    const float scale = 0.125f;  // C^-0.5
    const size_t abase = (size_t)bh * WW;
    #pragma unroll
    for (int iw = 0; iw < 4; iw++) {
        float4 r = make_float4(acc[iw][0]*scale, acc[iw][1]*scale,
                               acc[iw][2]*scale, acc[iw][3]*scale);
        *reinterpret_cast<float4*>(&g_attn[abase + (size_t)(w0+tx*4+iw)*Wn + v0+ty*4]) = r;
    }
    #pragma unroll
    for (int iv = 0; iv < 4; iv++) {
        float4 r = make_float4(acc[0][iv]*scale, acc[1][iv]*scale,
                               acc[2][iv]*scale, acc[3][iv]*scale);
        *reinterpret_cast<float4*>(&g_attnT[abase + (size_t)(v0+ty*4+iv)*Wn + w0+tx*4]) = r;
    }
}

// ============================================================
// K3/K4: 32-row tile per block; row softmax then F = P x V^T.
//   Warp mapping (compute phase): warp w -> 8 rows (w>>1),
//   1 channel per lane ((w&1)*32+lane). Halves per-lane f-load
//   smem traffic; P loads are warp-broadcast LDS128 (cheap).
//   Inner product uses packed f32x2 over v-pairs.
// ============================================================
#define RT 32                       // rows per block
#define VC 64                       // v-chunk width

__global__ __launch_bounds__(256,3) void k_apply(
    int dir,
    const float* __restrict__ xin,
    const float* __restrict__ coef,
    float* __restrict__ out)
{
    extern __shared__ float sm[];
    float* sp  = sm;                  // RT*320
    float* svc = sp + RT*Wn;          // VC*65   [v][c] padded
    float* so  = svc + VC*65;         // 64*33

    const float* __restrict__ P = dir ? g_attnT : g_attn;
    const float* __restrict__ V = dir ? g_Vl   : g_Vr;

    const int t    = threadIdx.x;
    const int lane = t & 31, wrp = t >> 5;
    const int r0   = blockIdx.x * RT;
    const int bh   = blockIdx.y;
    const int b    = bh / Hn, h = bh - b*Hn;
    const int vbase = b*CHW + h*Wn;
    const size_t pbase = (size_t)bh * WW + (size_t)r0 * Wn;

    // ---- load P tile (coalesced) ----
    #pragma unroll
    for (int i = 0; i < RT*Wn/256; i++)
        sp[t + i*256] = P[pbase + t + i*256];
    __syncthreads();

    // ---- softmax: warp wrp owns rows wrp*4 .. wrp*4+3 ----
    #pragma unroll
    for (int j = 0; j < 4; j++) {
        float* row = sp + (wrp*4 + j)*Wn;
        float e[10];
        float m = -1e30f;
        #pragma unroll
        for (int k = 0; k < 10; k++) { e[k] = row[lane + 32*k]; m = fmaxf(m, e[k]); }
        #pragma unroll
        for (int o = 16; o; o >>= 1) m = fmaxf(m, __shfl_xor_sync(0xffffffffu, m, o));
        float s = 0.f;
        #pragma unroll
        for (int k = 0; k < 10; k++) { e[k] = __expf(e[k] - m); s += e[k]; }
        #pragma unroll
        for (int o = 16; o; o >>= 1) s += __shfl_xor_sync(0xffffffffu, s, o);
        float inv = 1.f / s;
        #pragma unroll
        for (int k = 0; k < 10; k++) row[lane + 32*k] = e[k]*inv;
    }
    // (chunk-loop __syncthreads orders softmax writes before cross-warp reads)

    const int rowg = wrp >> 1;                    // 0..3 -> rows rowg*8..+8
    const int ch   = ((wrp & 1) << 5) + lane;     // 0..63

    // ---- F = P x V^T, streaming V in VC-wide chunks w/ reg prefetch ----
    float4 pf[4];
    #pragma unroll
    for (int q = 0; q < 4; q++) {
        int s = t + q*256;
        int c = s >> 4, vv4 = (s & 15) * 4;
        pf[q] = *reinterpret_cast<const float4*>(&V[vbase + c*HW + vv4]);
    }

    u64 acc2[8][2] = {};
    for (int cc = 0; cc < Wn/VC; cc++) {
        __syncthreads();   // previous chunk consumed (and softmax on cc=0)
        #pragma unroll
        for (int q = 0; q < 4; q++) {
            int s = t + q*256;
            int c = s >> 4, vv4 = (s & 15) * 4;
            svc[(vv4+0)*65 + c] = pf[q].x;
            svc[(vv4+1)*65 + c] = pf[q].y;
            svc[(vv4+2)*65 + c] = pf[q].z;
            svc[(vv4+3)*65 + c] = pf[q].w;
        }
        __syncthreads();

        if (cc < Wn/VC - 1) {
            int v0n = (cc+1)*VC;
            #pragma unroll
            for (int q = 0; q < 4; q++) {
                int s = t + q*256;
                int c = s >> 4, vv4 = (s & 15) * 4;
                pf[q] = *reinterpret_cast<const float4*>(&V[vbase + c*HW + v0n + vv4]);
            }
        }

        const int pco = cc*VC;
        #pragma unroll 2
        for (int v4 = 0; v4 < VC; v4 += 4) {
            float f0 = svc[(v4+0)*65 + ch];
            float f1 = svc[(v4+1)*65 + ch];
            float f2 = svc[(v4+2)*65 + ch];
            float f3 = svc[(v4+3)*65 + ch];
            u64 f01 = pack2(f0, f1), f23 = pack2(f2, f3);
            #pragma unroll
            for (int j = 0; j < 8; j++) {
                ulonglong2 pl = *reinterpret_cast<const ulonglong2*>(
                    &sp[(rowg*8+j)*Wn + pco + v4]);
                ffma2(acc2[j][0], pl.x, f01);
                ffma2(acc2[j][1], pl.y, f23);
            }
        }
    }

    // ---- reduce pairs, stage to smem, coalesced residual write ----
    #pragma unroll
    for (int j = 0; j < 8; j++) {
        float2 a = unpack2(acc2[j][0]);
        float2 c2 = unpack2(acc2[j][1]);
        so[ch*33 + rowg*8 + j] = (a.x+a.y) + (c2.x+c2.y);
    }
    __syncthreads();

    #pragma unroll
    for (int i = 0; i < Cn*RT/256; i++) {
        int idx = t + i*256;
        int c = idx >> 5, r = idx & (RT-1);
        int g = vbase + c*HW + r0 + r;
        out[g] = xin[g] + coef[c]*so[c*33 + r];
    }
}

// ============================================================
extern "C" void kernel_launch(void* const* d_in, const int* in_sizes, int n_in,
                              void* d_out, int out_size)
{
    const float* x_l   = (const float*)d_in[0];
    const float* x_r   = (const float*)d_in[1];
    const float* ln_l_w= (const float*)d_in[2];
    const float* ln_l_b= (const float*)d_in[3];
    const float* ln_r_w= (const float*)d_in[4];
    const float* ln_r_b= (const float*)d_in[5];
    const float* wq_l  = (const float*)d_in[6];
    const float* bq_l  = (const float*)d_in[7];
    const float* wq_r  = (const float*)d_in[8];
    const float* bq_r  = (const float*)d_in[9];
    const float* wv_l  = (const float*)d_in[10];
    const float* bv_l  = (const float*)d_in[11];
    const float* wv_r  = (const float*)d_in[12];
    const float* bv_r  = (const float*)d_in[13];
    const float* beta  = (const float*)d_in[14];
    const float* gamma = (const float*)d_in[15];
    float* out_l = (float*)d_out;
    float* out_r = out_l + BCHW;

    const int PROJ_SMEM  = (Cn*256 + 2*Cn*Cn + 3*Cn) * 4;          // 99072 B
    const int APPLY_SMEM = (RT*Wn + VC*65 + Cn*33) * 4;            // 66048 B

    cudaFuncSetAttribute(k_proj,  cudaFuncAttributeMaxDynamicSharedMemorySize, PROJ_SMEM);
    cudaFuncSetAttribute(k_apply, cudaFuncAttributeMaxDynamicSharedMemorySize, APPLY_SMEM);

    k_proj<<<Bn*HW/256, 256, PROJ_SMEM>>>(x_l, ln_l_w, ln_l_b, wq_l, bq_l, wv_l, bv_l, 0);
    k_proj<<<Bn*HW/256, 256, PROJ_SMEM>>>(x_r, ln_r_w, ln_r_b, wq_r, bq_r, wv_r, bv_r, 1);
    k_attn<<<dim3(Wn/64, Wn/64, BH), 256>>>();
    k_apply<<<dim3(Wn/RT, BH), 256, APPLY_SMEM>>>(0, x_l, beta,  out_l);
    k_apply<<<dim3(Wn/RT, BH), 256, APPLY_SMEM>>>(1, x_r, gamma, out_r);
}